// round 15
// baseline (speedup 1.0000x reference)
#include <cuda_runtime.h>

// Shapes fixed by the dataset: B=16, T=12 -> BT=192, N=512, Fin=Fout=64.
#define NN   512
#define FF   64
#define BTMAX 192

typedef unsigned long long ull;

// Scratch (device globals: allocation-free per harness rules)
__device__ float    g_Wh [(size_t)BTMAX * NN * FF];   // [bt][n][o]
__device__ float    g_Wh1[(size_t)BTMAX * NN];
__device__ float    g_Wh2[(size_t)BTMAX * NN];
__device__ unsigned g_mask[NN * 16];                  // 512 rows x 16 words of adjacency bits

// Packed f32x2 FMA (sm_100+): lo/hi lanes computed independently.
__device__ __forceinline__ ull ffma2(ull a, ull b, ull c) {
    ull d;
    asm("fma.rn.f32x2 %0, %1, %2, %3;" : "=l"(d) : "l"(a), "l"(b), "l"(c));
    return d;
}
__device__ __forceinline__ ull pack2(float lo, float hi) {
    ull r;
    asm("mov.b64 %0, {%1, %2};" : "=l"(r) : "f"(lo), "f"(hi));
    return r;
}
__device__ __forceinline__ float f2lo(ull v) { return __uint_as_float((unsigned)v); }
__device__ __forceinline__ float f2hi(ull v) { return __uint_as_float((unsigned)(v >> 32)); }

// Fast exp(x) for x <= 0 (clamped), poly-exp2 on fma/alu pipes (avoids MUFU bottleneck).
__device__ __forceinline__ float fexp(float x) {
    x = fmaxf(x, -87.0f);
    float t  = x * 1.4426950408889634f;          // log2(e)
    float fi = t + 12582912.0f;                  // round-to-nearest via magic
    int   i  = __float_as_int(fi) - 0x4B400000;  // integer part
    float f  = t - (fi - 12582912.0f);           // frac in [-0.5, 0.5]
    float p  = 1.3333558146e-3f;
    p = fmaf(p, f, 9.6181291076e-3f);
    p = fmaf(p, f, 5.5504108664e-2f);
    p = fmaf(p, f, 2.4022650695e-1f);
    p = fmaf(p, f, 6.9314718056e-1f);
    p = fmaf(p, f, 1.0f);                        // ~2^f
    return __int_as_float(__float_as_int(p) + (i << 23));
}

// ---------------------------------------------------------------------------
// Kernel 0: adjacency (512x512 float) -> bitmask (512x16 uint32)
// ---------------------------------------------------------------------------
__global__ void k_mask(const float* __restrict__ adj) {
    int w = blockIdx.x * blockDim.x + threadIdx.x;   // 0..8191
    int row = w >> 4, wi = w & 15;
    const float* arow = adj + row * NN + wi * 32;
    unsigned m = 0;
#pragma unroll
    for (int b = 0; b < 32; ++b)
        if (arow[b] > 0.f) m |= (1u << b);
    g_mask[w] = m;
}

// ---------------------------------------------------------------------------
// Kernel 1: Wh = h @ W (per bt), plus Wh1 = Wh@a1, Wh2 = Wh@a2.
// Grid (8, BT), 256 threads. f32x2-packed over k: acc lo = even-k, hi = odd-k.
// h_s[r][k] natural k-pairs (stride 68); W_T[o][k] transposed pairs (stride 66).
// ---------------------------------------------------------------------------
__global__ void __launch_bounds__(256)
k_wh(const float* __restrict__ h, const float* __restrict__ W,
     const float* __restrict__ a) {
    __shared__ float h_s[64 * 68];    // [r][k], 16B-aligned rows
    __shared__ float W_T[64 * 66];    // [o][k], 8B pair reads bank-conflict-free
    __shared__ float a_s[128];

    const int bt = blockIdx.y;
    const int i0 = blockIdx.x * 64;
    const int tid = threadIdx.x;

    // h rows (row-major, k contiguous -> natural pairs)
    const float4* hg4 = (const float4*)(h + ((size_t)bt * NN + i0) * FF);
    for (int e = tid; e < 1024; e += 256) {
        int r = e >> 4, q = e & 15;
        *(float4*)&h_s[r * 68 + 4 * q] = hg4[e];
    }
    // W transposed with k-pairs packed
    {
        int o = tid & 63, kg = tid >> 6;     // 4 groups x 16 k
#pragma unroll
        for (int u = 0; u < 8; ++u) {
            int k = kg * 16 + 2 * u;
            float w0 = W[k * FF + o];
            float w1 = W[(k + 1) * FF + o];
            *(ull*)&W_T[o * 66 + kg * 16 + 2 * u] = pack2(w0, w1);
        }
    }
    if (tid < 128) a_s[tid] = a[tid];
    __syncthreads();

    const int to = tid & 15;   // col base: owns o = to + 16c
    const int i4 = tid >> 4;   // row base: owns r = i4 + 16r'
    ull acc[4][4];
#pragma unroll
    for (int r = 0; r < 4; ++r)
#pragma unroll
        for (int c = 0; c < 4; ++c) acc[r][c] = 0ull;

#pragma unroll 8
    for (int m = 0; m < 32; ++m) {
        ull hv[4], wv[4];
#pragma unroll
        for (int r = 0; r < 4; ++r)
            hv[r] = *(const ull*)&h_s[(i4 + 16 * r) * 68 + 2 * m];
#pragma unroll
        for (int c = 0; c < 4; ++c)
            wv[c] = *(const ull*)&W_T[(to + 16 * c) * 66 + 2 * m];
#pragma unroll
        for (int r = 0; r < 4; ++r)
#pragma unroll
            for (int c = 0; c < 4; ++c)
                acc[r][c] = ffma2(hv[r], wv[c], acc[r][c]);
    }

    float val[4][4];
#pragma unroll
    for (int r = 0; r < 4; ++r)
#pragma unroll
        for (int c = 0; c < 4; ++c)
            val[r][c] = f2lo(acc[r][c]) + f2hi(acc[r][c]);

    float* og = g_Wh + ((size_t)bt * NN + i0) * FF;
#pragma unroll
    for (int r = 0; r < 4; ++r)
#pragma unroll
        for (int c = 0; c < 4; ++c)
            og[(i4 + 16 * r) * FF + to + 16 * c] = val[r][c];

    // Wh1/Wh2: per-row dots, reduce over the 16 to-lanes
#pragma unroll
    for (int r = 0; r < 4; ++r) {
        float s1 = 0.f, s2 = 0.f;
#pragma unroll
        for (int c = 0; c < 4; ++c) {
            s1 = fmaf(val[r][c], a_s[to + 16 * c], s1);
            s2 = fmaf(val[r][c], a_s[64 + to + 16 * c], s2);
        }
#pragma unroll
        for (int off = 8; off; off >>= 1) {
            s1 += __shfl_down_sync(0xffffffffu, s1, off, 16);
            s2 += __shfl_down_sync(0xffffffffu, s2, off, 16);
        }
        if (to == 0) {
            g_Wh1[(size_t)bt * NN + i0 + i4 + 16 * r] = s1;
            g_Wh2[(size_t)bt * NN + i0 + i4 + 16 * r] = s2;
        }
    }
}

// ---------------------------------------------------------------------------
// Kernel 2: fused attention. Grid (8, BT), 256 threads. f32x2-packed over j.
// Ps_T[i][j] and Wh_T[o][j] hold natural j-pairs (stride 66, conflict-free).
// ---------------------------------------------------------------------------
__global__ void __launch_bounds__(256)
k_attn(float* __restrict__ out) {
    __shared__ float    wh2s[NN];
    __shared__ float    wh1s[64];
    __shared__ float    ms[64];
    __shared__ float    lrs[64];
    __shared__ float    lps[256];
    __shared__ unsigned mask_s[64 * 17];
    __shared__ float    Ps_T[64 * 66];    // [i][j-local], paired over j
    __shared__ float    Wh_T[64 * 66];    // [o][j-local], paired over j

    const int bt = blockIdx.y;
    const int i0 = blockIdx.x * 64;
    const int tid = threadIdx.x;

    for (int e = tid; e < NN; e += 256) wh2s[e] = g_Wh2[(size_t)bt * NN + e];
    if (tid < 64) wh1s[tid] = g_Wh1[(size_t)bt * NN + i0 + tid];
    for (int w = tid; w < 1024; w += 256) {
        int r = w >> 4, c = w & 15;
        mask_s[r * 17 + c] = g_mask[(i0 + r) * 16 + c];
    }
    __syncthreads();

    // per-row softmax max: m_i = lrelu(Wh1_i + max_{j in adj(i)} Wh2_j)
    {
        int r = tid >> 2, q = tid & 3;
        float vmax = -1e30f;
#pragma unroll
        for (int w = 0; w < 4; ++w) {
            unsigned word = mask_s[r * 17 + q * 4 + w];
            int jb = (q * 4 + w) * 32;
#pragma unroll
            for (int b = 0; b < 32; ++b)
                if (word & (1u << b)) vmax = fmaxf(vmax, wh2s[jb + b]);
        }
        vmax = fmaxf(vmax, __shfl_xor_sync(0xffffffffu, vmax, 1, 4));
        vmax = fmaxf(vmax, __shfl_xor_sync(0xffffffffu, vmax, 2, 4));
        if (q == 0) {
            float s = wh1s[r] + vmax;
            ms[r] = (vmax < -1e29f) ? 0.f : (s > 0.f ? s : 0.2f * s);
        }
    }
    __syncthreads();

    const int pi = tid & 63, pg = tid >> 6;   // P-phase / transpose mapping
    const int i4 = tid >> 4, to = tid & 15;   // GEMM mapping (rows i4+16r, cols to+16c)
    const float w1   = wh1s[pi];
    const float mrow = ms[pi];

    ull acc[4][4];
#pragma unroll
    for (int r = 0; r < 4; ++r)
#pragma unroll
        for (int c = 0; c < 4; ++c) acc[r][c] = 0ull;
    float lp = 0.f;

    for (int jt = 0; jt < 8; ++jt) {
        // stage Wh column o=pi for 16 j's (coalesced across lanes), hide under P-phase
        float stg[16];
        const float* src = g_Wh + ((size_t)bt * NN + jt * 64 + pg * 16) * FF + pi;
#pragma unroll
        for (int s = 0; s < 16; ++s) stg[s] = src[s * FF];

        // P-phase: 16 j's for row pi, written as j-pairs
        unsigned word = mask_s[pi * 17 + jt * 2 + (pg >> 1)];
        int sh = (pg & 1) * 16;
#pragma unroll
        for (int t8 = 0; t8 < 8; ++t8) {
            int jj0 = 2 * t8;
            float s0 = w1 + wh2s[jt * 64 + pg * 16 + jj0];
            float e0 = s0 > 0.f ? s0 : 0.2f * s0;
            float p0 = ((word >> (sh + jj0)) & 1u) ? fexp(e0 - mrow) : 0.f;
            float s1 = w1 + wh2s[jt * 64 + pg * 16 + jj0 + 1];
            float e1 = s1 > 0.f ? s1 : 0.2f * s1;
            float p1 = ((word >> (sh + jj0 + 1)) & 1u) ? fexp(e1 - mrow) : 0.f;
            lp += p0 + p1;
            *(ull*)&Ps_T[pi * 66 + pg * 16 + 2 * t8] = pack2(p0, p1);
        }
        // store staged Wh as transposed j-pairs
#pragma unroll
        for (int u = 0; u < 8; ++u)
            *(ull*)&Wh_T[pi * 66 + pg * 16 + 2 * u] = pack2(stg[2 * u], stg[2 * u + 1]);
        __syncthreads();

        // GEMM: 32 j-pairs, acc lo=even-j, hi=odd-j
#pragma unroll 8
        for (int m = 0; m < 32; ++m) {
            ull pv[4], wv[4];
#pragma unroll
            for (int r = 0; r < 4; ++r)
                pv[r] = *(const ull*)&Ps_T[(i4 + 16 * r) * 66 + 2 * m];
#pragma unroll
            for (int c = 0; c < 4; ++c)
                wv[c] = *(const ull*)&Wh_T[(to + 16 * c) * 66 + 2 * m];
#pragma unroll
            for (int r = 0; r < 4; ++r)
#pragma unroll
                for (int c = 0; c < 4; ++c)
                    acc[r][c] = ffma2(pv[r], wv[c], acc[r][c]);
        }
        __syncthreads();
    }

    // reduce l_i across the 4 j-groups
    lps[tid] = lp;
    __syncthreads();
    if (tid < 64) {
        float l = lps[tid] + lps[tid + 64] + lps[tid + 128] + lps[tid + 192];
        lrs[tid] = (l > 0.f) ? 1.f / l : 0.f;
    }
    __syncthreads();

    // epilogue: merge halves, normalize, ELU
    float* og = out + ((size_t)bt * NN + i0) * FF;
#pragma unroll
    for (int r = 0; r < 4; ++r) {
        int i = i4 + 16 * r;
        float inv = lrs[i];
#pragma unroll
        for (int c = 0; c < 4; ++c) {
            float v = (f2lo(acc[r][c]) + f2hi(acc[r][c])) * inv;
            v = v > 0.f ? v : fexp(v) - 1.f;
            og[i * FF + to + 16 * c] = v;
        }
    }
}

// ---------------------------------------------------------------------------
extern "C" void kernel_launch(void* const* d_in, const int* in_sizes, int n_in,
                              void* d_out, int out_size) {
    const float* h   = (const float*)d_in[0];
    const float* adj = (const float*)d_in[1];
    const float* W   = (const float*)d_in[2];
    const float* a   = (const float*)d_in[3];
    int BT = in_sizes[0] / (NN * FF);   // 192 for this dataset

    k_mask<<<32, 256>>>(adj);
    k_wh  <<<dim3(8, BT), 256>>>(h, W, a);
    k_attn<<<dim3(8, BT), 256>>>((float*)d_out);
}